// round 14
// baseline (speedup 1.0000x reference)
#include <cuda_runtime.h>
#include <cuda_fp16.h>
#include <math.h>
#include <stdint.h>

#define D_MODEL 1024
#define N_TOK   8192
#define FF_DIM  4096
#define N_HEAD  16
#define HEAD_D  64

__device__ __half g_h  [N_TOK * D_MODEL];
__device__ __half g_qkv[N_TOK * 3 * D_MODEL];
__device__ __half g_ctx[N_TOK * D_MODEL];
__device__ float  g_x2 [N_TOK * D_MODEL];
__device__ __half g_ff [N_TOK * FF_DIM];
__device__ __half g_wq[3 * D_MODEL * D_MODEL];
__device__ __half g_wp[D_MODEL * D_MODEL];
__device__ __half g_w1[FF_DIM * D_MODEL];
__device__ __half g_w2[D_MODEL * FF_DIM];

// q pre-scale: 1/sqrt(64) * log2(e)
#define QSC 0.18033688011112042f

// ---------------- helpers ----------------
__device__ __forceinline__ float gelu_exact(float v) {
    return 0.5f * v * (1.0f + erff(v * 0.70710678118654752440f));
}
__device__ __forceinline__ float ex2(float x) {
    float r;
    asm("ex2.approx.ftz.f32 %0, %1;" : "=f"(r) : "f"(x));
    return r;
}
__device__ __forceinline__ void mma_f16(float d[4], uint32_t a0, uint32_t a1,
                                        uint32_t a2, uint32_t a3,
                                        uint32_t b0, uint32_t b1) {
    asm volatile(
        "mma.sync.aligned.m16n8k16.row.col.f32.f16.f16.f32 "
        "{%0,%1,%2,%3}, {%4,%5,%6,%7}, {%8,%9}, {%0,%1,%2,%3};\n"
        : "+f"(d[0]), "+f"(d[1]), "+f"(d[2]), "+f"(d[3])
        : "r"(a0), "r"(a1), "r"(a2), "r"(a3), "r"(b0), "r"(b1));
}
__device__ __forceinline__ void ldsm4(uint32_t& r0, uint32_t& r1, uint32_t& r2,
                                      uint32_t& r3, uint32_t addr) {
    asm volatile("ldmatrix.sync.aligned.m8n8.x4.shared.b16 {%0,%1,%2,%3}, [%4];"
                 : "=r"(r0), "=r"(r1), "=r"(r2), "=r"(r3) : "r"(addr));
}
__device__ __forceinline__ void ldsm4t(uint32_t& r0, uint32_t& r1, uint32_t& r2,
                                       uint32_t& r3, uint32_t addr) {
    asm volatile("ldmatrix.sync.aligned.m8n8.x4.trans.shared.b16 {%0,%1,%2,%3}, [%4];"
                 : "=r"(r0), "=r"(r1), "=r"(r2), "=r"(r3) : "r"(addr));
}
__device__ __forceinline__ void cp16(uint32_t smem, const void* g) {
    asm volatile("cp.async.cg.shared.global [%0], [%1], 16;" :: "r"(smem), "l"(g));
}
__device__ __forceinline__ void cp_commit() {
    asm volatile("cp.async.commit_group;");
}
__device__ __forceinline__ void cp_wait2() {
    asm volatile("cp.async.wait_group 2;");
}
__device__ __forceinline__ void cp_wait0() {
    asm volatile("cp.async.wait_group 0;");
}
__device__ __forceinline__ uint32_t pack2(float a, float b) {
    __half2 h = __floats2half2_rn(a, b);
    return *(uint32_t*)&h;
}

// ---------------- fused weight convert fp32 -> fp16 ----------------
#define WQ_Q 786432
#define WP_Q 262144
#define W1_Q 1048576
#define W2_Q 1048576
#define TOT_Q (WQ_Q + WP_Q + W1_Q + W2_Q)

__global__ void __launch_bounds__(256) conv_all(const float* __restrict__ qw,
                                                const float* __restrict__ pw,
                                                const float* __restrict__ w1,
                                                const float* __restrict__ w2,
                                                __half* __restrict__ oq,
                                                __half* __restrict__ op,
                                                __half* __restrict__ o1,
                                                __half* __restrict__ o2) {
    int i = blockIdx.x * 256 + threadIdx.x;
    const float* src; __half* dst; int off;
    if (i < WQ_Q) { src = qw; dst = oq; off = i; }
    else if (i < WQ_Q + WP_Q) { src = pw; dst = op; off = i - WQ_Q; }
    else if (i < WQ_Q + WP_Q + W1_Q) { src = w1; dst = o1; off = i - WQ_Q - WP_Q; }
    else { src = w2; dst = o2; off = i - WQ_Q - WP_Q - W1_Q; }
    float4 v = ((const float4*)src)[off];
    uint2 o;
    o.x = pack2(v.x, v.y);
    o.y = pack2(v.z, v.w);
    ((uint2*)dst)[off] = o;
}

// ---------------- LayerNorm: one WARP per row ----------------
__global__ void __launch_bounds__(256) ln_kernel(const float* __restrict__ x,
                                                 const float* __restrict__ g,
                                                 const float* __restrict__ b,
                                                 __half* __restrict__ out) {
    int warp = threadIdx.x >> 5, lane = threadIdx.x & 31;
    int row = blockIdx.x * 8 + warp;
    const float4* xr = (const float4*)(x + (size_t)row * D_MODEL);
    const float4* gr = (const float4*)g;
    const float4* br = (const float4*)b;
    uint2* orow = (uint2*)(out + (size_t)row * D_MODEL);

    float4 v[8];
    #pragma unroll
    for (int i = 0; i < 8; ++i) v[i] = xr[lane + 32 * i];

    float s = 0.f, sq = 0.f;
    #pragma unroll
    for (int i = 0; i < 8; ++i) {
        s  += v[i].x + v[i].y + v[i].z + v[i].w;
        sq += v[i].x*v[i].x + v[i].y*v[i].y + v[i].z*v[i].z + v[i].w*v[i].w;
    }
    #pragma unroll
    for (int o = 16; o > 0; o >>= 1) {
        s  += __shfl_xor_sync(0xffffffffu, s,  o);
        sq += __shfl_xor_sync(0xffffffffu, sq, o);
    }
    float mu = s * (1.0f / D_MODEL);
    float var = sq * (1.0f / D_MODEL) - mu * mu;
    float rstd = rsqrtf(var + 1e-6f);

    #pragma unroll
    for (int i = 0; i < 8; ++i) {
        float4 gv = gr[lane + 32 * i];
        float4 bv = br[lane + 32 * i];
        float v0 = (v[i].x - mu) * rstd * gv.x + bv.x;
        float v1 = (v[i].y - mu) * rstd * gv.y + bv.y;
        float v2 = (v[i].z - mu) * rstd * gv.z + bv.z;
        float v3 = (v[i].w - mu) * rstd * gv.w + bv.w;
        uint2 o;
        o.x = pack2(v0, v1);
        o.y = pack2(v2, v3);
        orow[lane + 32 * i] = o;
    }
}

// ---------------- FP16 GEMM: 256x128 CTA, 256 threads, 64x64 warp tiles ----
// 8 warps (2 per SMSP): warps 0-3 cover M rows, warps 4-7 the other N half.
#define BM2 256
#define BN 128
#define BKH 32
#define PITCHB 80
#define STAGES 4
#define A_SZ (BM2 * PITCHB)                // 20480
#define STAGE_BYTES (A_SZ + BN * PITCHB)   // 30720

template<int EPI, int OUTHALF, int QSCALE>
__global__ void __launch_bounds__(256, 1) gemm_h(const __half* __restrict__ A,
                                                 const __half* __restrict__ Bw,
                                                 const float* __restrict__ bias,
                                                 const float* __restrict__ res,
                                                 void* __restrict__ Cout,
                                                 int M, int N, int K) {
    extern __shared__ char smraw[];
    uint32_t su = (uint32_t)__cvta_generic_to_shared(smraw);

    int tid = threadIdx.x;
    int m0 = blockIdx.y * BM2;
    int n0 = blockIdx.x * BN;
    int warp = tid >> 5, lane = tid & 31;
    int wm = (warp & 3) * 64;
    int wn = (warp >> 2) * 64;
    int r4 = lane >> 2, cc = lane & 3;

    float acc[4][8][4];
    #pragma unroll
    for (int i = 0; i < 4; ++i)
        #pragma unroll
        for (int j = 0; j < 8; ++j)
            #pragma unroll
            for (int k = 0; k < 4; ++k) acc[i][j][k] = 0.f;

    // A loader: row = tid (0..255), 4 cp16 (64B)
    const __half* Ap = A + (size_t)(m0 + tid) * K;
    uint32_t dA = (uint32_t)(tid * PITCHB);
    // B loader: row = tid>>1 (0..127), half = tid&1, 2 cp16
    int brow = tid >> 1, bpr = tid & 1;
    const __half* Bp = Bw + (size_t)(n0 + brow) * K + bpr * 16;
    uint32_t dB = (uint32_t)(A_SZ + brow * PITCHB + bpr * 32);

    uint32_t aAddr = su + (uint32_t)((wm + (lane & 15)) * PITCHB + (lane >> 4) * 16);
    uint32_t bAddr = su + A_SZ +
        (uint32_t)((wn + (lane & 7) + ((lane >> 4) << 3)) * PITCHB +
                   ((lane >> 3) & 1) * 16);

    int ntiles = K / BKH;

    #pragma unroll
    for (int s = 0; s < STAGES - 1; ++s) {
        uint32_t sb = su + s * STAGE_BYTES;
        const __half* a = Ap + s * BKH;
        const __half* b = Bp + s * BKH;
        #pragma unroll
        for (int j = 0; j < 4; ++j) cp16(sb + dA + j * 16, a + j * 8);
        cp16(sb + dB, b);
        cp16(sb + dB + 16, b + 8);
        cp_commit();
    }

    for (int t = 0; t < ntiles; ++t) {
        cp_wait2();
        __syncthreads();

        int tp = t + STAGES - 1;
        if (tp < ntiles) {
            uint32_t sb = su + (tp & (STAGES - 1)) * STAGE_BYTES;
            const __half* a = Ap + tp * BKH;
            const __half* b = Bp + tp * BKH;
            #pragma unroll
            for (int j = 0; j < 4; ++j) cp16(sb + dA + j * 16, a + j * 8);
            cp16(sb + dB, b);
            cp16(sb + dB + 16, b + 8);
        }
        cp_commit();

        uint32_t stg = (t & (STAGES - 1)) * STAGE_BYTES;
        #pragma unroll
        for (int ks = 0; ks < 2; ++ks) {
            uint32_t kof = stg + ks * 32;
            uint32_t af[4][4], bf[8][2];
            #pragma unroll
            for (int mt = 0; mt < 4; ++mt)
                ldsm4(af[mt][0], af[mt][1], af[mt][2], af[mt][3],
                      aAddr + kof + mt * (16 * PITCHB));
            #pragma unroll
            for (int nb = 0; nb < 4; ++nb)
                ldsm4(bf[2*nb][0], bf[2*nb][1], bf[2*nb+1][0], bf[2*nb+1][1],
                      bAddr + kof + nb * (16 * PITCHB));
            #pragma unroll
            for (int mt = 0; mt < 4; ++mt)
                #pragma unroll
                for (int nt = 0; nt < 8; ++nt)
                    mma_f16(acc[mt][nt], af[mt][0], af[mt][1], af[mt][2], af[mt][3],
                            bf[nt][0], bf[nt][1]);
        }
    }

    #pragma unroll
    for (int mt = 0; mt < 4; ++mt) {
        int row0 = m0 + wm + mt * 16 + r4;
        #pragma unroll
        for (int nt = 0; nt < 8; ++nt) {
            int col = n0 + wn + nt * 8 + cc * 2;
            float b0v = bias[col], b1v = bias[col + 1];
            float v0 = acc[mt][nt][0] + b0v;
            float v1 = acc[mt][nt][1] + b1v;
            float v2 = acc[mt][nt][2] + b0v;
            float v3 = acc[mt][nt][3] + b1v;
            if (EPI == 1) {
                v0 = gelu_exact(v0); v1 = gelu_exact(v1);
                v2 = gelu_exact(v2); v3 = gelu_exact(v3);
            }
            if (EPI == 2) {
                float2 r0 = *(const float2*)&res[(size_t)row0 * N + col];
                float2 r1 = *(const float2*)&res[(size_t)(row0 + 8) * N + col];
                v0 += r0.x; v1 += r0.y; v2 += r1.x; v3 += r1.y;
            }
            if (QSCALE) {
                if (col < 1024) {
                    v0 *= QSC; v1 *= QSC; v2 *= QSC; v3 *= QSC;
                }
            }
            if (OUTHALF) {
                __half* Ch = (__half*)Cout;
                *(uint32_t*)&Ch[(size_t)row0 * N + col]       = pack2(v0, v1);
                *(uint32_t*)&Ch[(size_t)(row0 + 8) * N + col] = pack2(v2, v3);
            } else {
                float* Cf = (float*)Cout;
                *(float2*)&Cf[(size_t)row0 * N + col]       = make_float2(v0, v1);
                *(float2*)&Cf[(size_t)(row0 + 8) * N + col] = make_float2(v2, v3);
            }
        }
    }
}

// ---------------- FP16 flash attention (frozen from R12/13) ------
#define HP 72
#define Q_BYTES  (128 * HP * 2)
#define KV_STB   (64 * HP * 2)
#define KO_BYTES Q_BYTES
#define VO_BYTES (Q_BYTES + 2 * KV_STB)
#define ATTN_SMEM (Q_BYTES + 4 * KV_STB)

__global__ void __launch_bounds__(256) attn_h(const __half* __restrict__ qkv,
                                              __half* __restrict__ ctx) {
    extern __shared__ char asm_raw[];
    uint32_t base = (uint32_t)__cvta_generic_to_shared(asm_raw);

    int t = threadIdx.x;
    int warp = t >> 5, lane = t & 31;
    int r4 = lane >> 2, cc = lane & 3;
    int b = blockIdx.z, h = blockIdx.y;
    int s0 = blockIdx.x * 128;
    int wq = warp * 16;

    const __half* qbase = qkv + (size_t)(b * 1024 + s0) * 3072 + h * HEAD_D;
    const __half* kbase = qkv + (size_t)b * 1024 * 3072 + 1024 + h * HEAD_D;
    const __half* vbase = qkv + (size_t)b * 1024 * 3072 + 2048 + h * HEAD_D;

    #pragma unroll
    for (int p = 0; p < 4; ++p) {
        int j = t + 256 * p;
        int row = j >> 3, ch = j & 7;
        cp16(base + row * 144 + ch * 16, qbase + (size_t)row * 3072 + ch * 8);
    }
    #pragma unroll
    for (int p = 0; p < 2; ++p) {
        int j = t + 256 * p;
        int row = j >> 3, ch = j & 7;
        cp16(base + KO_BYTES + row * 144 + ch * 16,
             kbase + (size_t)row * 3072 + ch * 8);
        cp16(base + VO_BYTES + row * 144 + ch * 16,
             vbase + (size_t)row * 3072 + ch * 8);
    }
    cp_commit();

    uint32_t aQ = base + (uint32_t)((wq + (lane & 15)) * 144 + (lane >> 4) * 16);
    uint32_t bKoff = (uint32_t)(((lane & 7) + ((lane >> 4) << 3)) * 144 +
                                ((lane >> 3) & 1) * 16);
    int tsel = lane >> 3, tr = lane & 7;
    uint32_t bVoff = (uint32_t)(((tsel & 1) * 8 + tr) * 144 + (tsel >> 1) * 16);

    uint32_t qf[4][4];
    float mr_lo = -1e30f, mr_hi = -1e30f, l_lo = 0.f, l_hi = 0.f;
    float oacc[8][4];
    #pragma unroll
    for (int i = 0; i < 8; ++i)
        #pragma unroll
        for (int j = 0; j < 4; ++j) oacc[i][j] = 0.f;

    for (int it = 0; it < 16; ++it) {
        cp_wait0();
        __syncthreads();

        if (it + 1 < 16) {
            uint32_t st = ((it + 1) & 1) * KV_STB;
            const __half* kp = kbase + (size_t)(it + 1) * 64 * 3072;
            const __half* vp = vbase + (size_t)(it + 1) * 64 * 3072;
            #pragma unroll
            for (int p = 0; p < 2; ++p) {
                int j = t + 256 * p;
                int row = j >> 3, ch = j & 7;
                cp16(base + KO_BYTES + st + row * 144 + ch * 16,
                     kp + (size_t)row * 3072 + ch * 8);
                cp16(base + VO_BYTES + st + row * 144 + ch * 16,
                     vp + (size_t)row * 3072 + ch * 8);
            }
            cp_commit();
        }

        if (it == 0) {
            #pragma unroll
            for (int ks = 0; ks < 4; ++ks)
                ldsm4(qf[ks][0], qf[ks][1], qf[ks][2], qf[ks][3], aQ + ks * 32);
        }

        uint32_t stg = (it & 1) * KV_STB;
        uint32_t bK = base + KO_BYTES + stg + bKoff;
        uint32_t bV = base + VO_BYTES + stg + bVoff;

        float sacc[8][4];
        #pragma unroll
        for (int i = 0; i < 8; ++i)
            #pragma unroll
            for (int j = 0; j < 4; ++j) sacc[i][j] = 0.f;

        #pragma unroll
        for (int ks = 0; ks < 4; ++ks) {
            uint32_t bf[8][2];
            #pragma unroll
            for (int nb = 0; nb < 4; ++nb)
                ldsm4(bf[2*nb][0], bf[2*nb][1], bf[2*nb+1][0], bf[2*nb+1][1],
                      bK + nb * (16 * 144) + ks * 32);
            #pragma unroll
            for (int nt = 0; nt < 8; ++nt)
                mma_f16(sacc[nt], qf[ks][0], qf[ks][1], qf[ks][2], qf[ks][3],
                        bf[nt][0], bf[nt][1]);
        }

        float mlo = -1e30f, mhi = -1e30f;
        #pragma unroll
        for (int nt = 0; nt < 8; ++nt) {
            mlo = fmaxf(mlo, fmaxf(sacc[nt][0], sacc[nt][1]));
            mhi = fmaxf(mhi, fmaxf(sacc[nt][2], sacc[nt][3]));
        }
        mlo = fmaxf(mlo, __shfl_xor_sync(0xffffffffu, mlo, 1));
        mlo = fmaxf(mlo, __shfl_xor_sync(0xffffffffu, mlo, 2));
        mhi = fmaxf(mhi, __shfl_xor_sync(0xffffffffu, mhi, 1));
        mhi = fmaxf(mhi, __shfl_xor_sync(0xffffffffu, mhi, 2));
        float mn_lo = fmaxf(mr_lo, mlo), mn_hi = fmaxf(mr_hi, mhi);
        float al_lo = ex2(mr_lo - mn_lo), al_hi = ex2(mr_hi - mn_hi);

        float ps_lo = 0.f, ps_hi = 0.f;
        #pragma unroll
        for (int nt = 0; nt < 8; ++nt) {
            sacc[nt][0] = ex2(sacc[nt][0] - mn_lo);
            sacc[nt][1] = ex2(sacc[nt][1] - mn_lo);
            sacc[nt][2] = ex2(sacc[nt][2] - mn_hi);
            sacc[nt][3] = ex2(sacc[nt][3] - mn_hi);
            ps_lo += sacc[nt][0] + sacc[nt][1];
            ps_hi += sacc[nt][2] + sacc[nt][3];
        }
        ps_lo += __shfl_xor_sync(0xffffffffu, ps_lo, 1);
        ps_lo += __shfl_xor_sync(0xffffffffu, ps_lo, 2);
        ps_hi += __shfl_xor_sync(0xffffffffu, ps_hi, 1);
        ps_hi += __shfl_xor_sync(0xffffffffu, ps_hi, 2);
        l_lo = l_lo * al_lo + ps_lo;
        l_hi = l_hi * al_hi + ps_hi;
        mr_lo = mn_lo; mr_hi = mn_hi;
        #pragma unroll
        for (int nt = 0; nt < 8; ++nt) {
            oacc[nt][0] *= al_lo; oacc[nt][1] *= al_lo;
            oacc[nt][2] *= al_hi; oacc[nt][3] *= al_hi;
        }

        #pragma unroll
        for (int kk = 0; kk < 4; ++kk) {
            uint32_t a0 = pack2(sacc[2*kk][0],   sacc[2*kk][1]);
            uint32_t a1 = pack2(sacc[2*kk][2],   sacc[2*kk][3]);
            uint32_t a2 = pack2(sacc[2*kk+1][0], sacc[2*kk+1][1]);
            uint32_t a3 = pack2(sacc[2*kk+1][2], sacc[2*kk+1][3]);
            uint32_t vf[8][2];
            #pragma unroll
            for (int db = 0; db < 4; ++db)
                ldsm4t(vf[2*db][0], vf[2*db][1], vf[2*db+1][0], vf[2*db+1][1],
                       bV + kk * (16 * 144) + db * 32);
            #pragma unroll
            for (int nt = 0; nt < 8; ++nt)
                mma_f16(oacc[nt], a0, a1, a2, a3, vf[nt][0], vf[nt][1]);
        }
    }

    float il_lo = 1.f / l_lo, il_hi = 1.f / l_hi;
    int row_lo = b * 1024 + s0 + wq + r4;
    #pragma unroll
    for (int nt = 0; nt < 8; ++nt) {
        int col = h * HEAD_D + nt * 8 + cc * 2;
        *(uint32_t*)&ctx[(size_t)row_lo * D_MODEL + col] =
            pack2(oacc[nt][0] * il_lo, oacc[nt][1] * il_lo);
        *(uint32_t*)&ctx[(size_t)(row_lo + 8) * D_MODEL + col] =
            pack2(oacc[nt][2] * il_hi, oacc[nt][3] * il_hi);
    }
}

// ---------------- launch ----------------
extern "C" void kernel_launch(void* const* d_in, const int* in_sizes, int n_in,
                              void* d_out, int out_size) {
    const float* x      = (const float*)d_in[0];
    const float* qkv_w  = (const float*)d_in[1];
    const float* qkv_b  = (const float*)d_in[2];
    const float* proj_w = (const float*)d_in[3];
    const float* proj_b = (const float*)d_in[4];
    const float* fc1_w  = (const float*)d_in[5];
    const float* fc1_b  = (const float*)d_in[6];
    const float* fc2_w  = (const float*)d_in[7];
    const float* fc2_b  = (const float*)d_in[8];
    const float* ln1_g  = (const float*)d_in[9];
    const float* ln1_b  = (const float*)d_in[10];
    const float* ln2_g  = (const float*)d_in[11];
    const float* ln2_b  = (const float*)d_in[12];
    float* out = (float*)d_out;

    __half *h, *qkv, *ctx, *ff, *wq, *wp, *w1, *w2;
    float *x2;
    cudaGetSymbolAddress((void**)&h,   g_h);
    cudaGetSymbolAddress((void**)&qkv, g_qkv);
    cudaGetSymbolAddress((void**)&ctx, g_ctx);
    cudaGetSymbolAddress((void**)&x2,  g_x2);
    cudaGetSymbolAddress((void**)&ff,  g_ff);
    cudaGetSymbolAddress((void**)&wq,  g_wq);
    cudaGetSymbolAddress((void**)&wp,  g_wp);
    cudaGetSymbolAddress((void**)&w1,  g_w1);
    cudaGetSymbolAddress((void**)&w2,  g_w2);

    int gemm_smem = STAGES * STAGE_BYTES;   // 122880
    cudaFuncSetAttribute(gemm_h<0,1,1>, cudaFuncAttributeMaxDynamicSharedMemorySize, gemm_smem);
    cudaFuncSetAttribute(gemm_h<2,0,0>, cudaFuncAttributeMaxDynamicSharedMemorySize, gemm_smem);
    cudaFuncSetAttribute(gemm_h<1,1,0>, cudaFuncAttributeMaxDynamicSharedMemorySize, gemm_smem);
    cudaFuncSetAttribute(attn_h, cudaFuncAttributeMaxDynamicSharedMemorySize, ATTN_SMEM);

    conv_all<<<TOT_Q / 256, 256>>>(qkv_w, proj_w, fc1_w, fc2_w, wq, wp, w1, w2);

    ln_kernel<<<N_TOK / 8, 256>>>(x, ln1_g, ln1_b, h);
    gemm_h<0,1,1><<<dim3(3 * D_MODEL / BN, N_TOK / BM2), 256, gemm_smem>>>(
        h, wq, qkv_b, nullptr, qkv, N_TOK, 3 * D_MODEL, D_MODEL);
    attn_h<<<dim3(1024 / 128, N_HEAD, 8), 256, ATTN_SMEM>>>(qkv, ctx);
    gemm_h<2,0,0><<<dim3(D_MODEL / BN, N_TOK / BM2), 256, gemm_smem>>>(
        ctx, wp, proj_b, x, x2, N_TOK, D_MODEL, D_MODEL);
    ln_kernel<<<N_TOK / 8, 256>>>(x2, ln2_g, ln2_b, h);
    gemm_h<1,1,0><<<dim3(FF_DIM / BN, N_TOK / BM2), 256, gemm_smem>>>(
        h, w1, fc1_b, nullptr, ff, N_TOK, FF_DIM, D_MODEL);
    gemm_h<2,0,0><<<dim3(D_MODEL / BN, N_TOK / BM2), 256, gemm_smem>>>(
        ff, w2, fc2_b, x2, out, N_TOK, D_MODEL, FF_DIM);
}

// round 15
// speedup vs baseline: 1.2055x; 1.2055x over previous
#include <cuda_runtime.h>
#include <cuda_fp16.h>
#include <math.h>
#include <stdint.h>

#define D_MODEL 1024
#define N_TOK   8192
#define FF_DIM  4096
#define N_HEAD  16
#define HEAD_D  64

__device__ __half g_h  [N_TOK * D_MODEL];
__device__ __half g_qkv[N_TOK * 3 * D_MODEL];
__device__ __half g_ctx[N_TOK * D_MODEL];
__device__ float  g_x2 [N_TOK * D_MODEL];
__device__ __half g_ff [N_TOK * FF_DIM];
__device__ __half g_wq[3 * D_MODEL * D_MODEL];
__device__ __half g_wp[D_MODEL * D_MODEL];
__device__ __half g_w1[FF_DIM * D_MODEL];
__device__ __half g_w2[D_MODEL * FF_DIM];

// q pre-scale: 1/sqrt(64) * log2(e)
#define QSC 0.18033688011112042f

// ---------------- helpers ----------------
__device__ __forceinline__ float gelu_exact(float v) {
    return 0.5f * v * (1.0f + erff(v * 0.70710678118654752440f));
}
__device__ __forceinline__ float ex2(float x) {
    float r;
    asm("ex2.approx.ftz.f32 %0, %1;" : "=f"(r) : "f"(x));
    return r;
}
__device__ __forceinline__ void mma_f16(float d[4], uint32_t a0, uint32_t a1,
                                        uint32_t a2, uint32_t a3,
                                        uint32_t b0, uint32_t b1) {
    asm volatile(
        "mma.sync.aligned.m16n8k16.row.col.f32.f16.f16.f32 "
        "{%0,%1,%2,%3}, {%4,%5,%6,%7}, {%8,%9}, {%0,%1,%2,%3};\n"
        : "+f"(d[0]), "+f"(d[1]), "+f"(d[2]), "+f"(d[3])
        : "r"(a0), "r"(a1), "r"(a2), "r"(a3), "r"(b0), "r"(b1));
}
__device__ __forceinline__ void ldsm4(uint32_t& r0, uint32_t& r1, uint32_t& r2,
                                      uint32_t& r3, uint32_t addr) {
    asm volatile("ldmatrix.sync.aligned.m8n8.x4.shared.b16 {%0,%1,%2,%3}, [%4];"
                 : "=r"(r0), "=r"(r1), "=r"(r2), "=r"(r3) : "r"(addr));
}
__device__ __forceinline__ void ldsm4t(uint32_t& r0, uint32_t& r1, uint32_t& r2,
                                       uint32_t& r3, uint32_t addr) {
    asm volatile("ldmatrix.sync.aligned.m8n8.x4.trans.shared.b16 {%0,%1,%2,%3}, [%4];"
                 : "=r"(r0), "=r"(r1), "=r"(r2), "=r"(r3) : "r"(addr));
}
__device__ __forceinline__ void cp16(uint32_t smem, const void* g) {
    asm volatile("cp.async.cg.shared.global [%0], [%1], 16;" :: "r"(smem), "l"(g));
}
__device__ __forceinline__ void cp_commit() {
    asm volatile("cp.async.commit_group;");
}
__device__ __forceinline__ void cp_wait3() {
    asm volatile("cp.async.wait_group 3;");
}
__device__ __forceinline__ void cp_wait0() {
    asm volatile("cp.async.wait_group 0;");
}
__device__ __forceinline__ uint32_t pack2(float a, float b) {
    __half2 h = __floats2half2_rn(a, b);
    return *(uint32_t*)&h;
}

// ---------------- fused prep: weight convert + LN1 in one launch ----------
#define WQ_Q 786432
#define WP_Q 262144
#define W1_Q 1048576
#define W2_Q 1048576
#define TOT_Q (WQ_Q + WP_Q + W1_Q + W2_Q)   // 3145728
#define CONV_BLOCKS (TOT_Q / 256)            // 12288
#define LN_BLOCKS   (N_TOK / 8)              // 1024

__global__ void __launch_bounds__(256) prep_kernel(
        const float* __restrict__ qw, const float* __restrict__ pw,
        const float* __restrict__ w1, const float* __restrict__ w2,
        __half* __restrict__ oq, __half* __restrict__ op,
        __half* __restrict__ o1, __half* __restrict__ o2,
        const float* __restrict__ x, const float* __restrict__ lg,
        const float* __restrict__ lb, __half* __restrict__ hout) {
    if (blockIdx.x < CONV_BLOCKS) {
        int i = blockIdx.x * 256 + threadIdx.x;
        const float* src; __half* dst; int off;
        if (i < WQ_Q) { src = qw; dst = oq; off = i; }
        else if (i < WQ_Q + WP_Q) { src = pw; dst = op; off = i - WQ_Q; }
        else if (i < WQ_Q + WP_Q + W1_Q) { src = w1; dst = o1; off = i - WQ_Q - WP_Q; }
        else { src = w2; dst = o2; off = i - WQ_Q - WP_Q - W1_Q; }
        float4 v = ((const float4*)src)[off];
        uint2 o;
        o.x = pack2(v.x, v.y);
        o.y = pack2(v.z, v.w);
        ((uint2*)dst)[off] = o;
    } else {
        int warp = threadIdx.x >> 5, lane = threadIdx.x & 31;
        int row = (blockIdx.x - CONV_BLOCKS) * 8 + warp;
        const float4* xr = (const float4*)(x + (size_t)row * D_MODEL);
        const float4* gr = (const float4*)lg;
        const float4* br = (const float4*)lb;
        uint2* orow = (uint2*)(hout + (size_t)row * D_MODEL);

        float4 v[8];
        #pragma unroll
        for (int i = 0; i < 8; ++i) v[i] = xr[lane + 32 * i];
        float s = 0.f, sq = 0.f;
        #pragma unroll
        for (int i = 0; i < 8; ++i) {
            s  += v[i].x + v[i].y + v[i].z + v[i].w;
            sq += v[i].x*v[i].x + v[i].y*v[i].y + v[i].z*v[i].z + v[i].w*v[i].w;
        }
        #pragma unroll
        for (int o = 16; o > 0; o >>= 1) {
            s  += __shfl_xor_sync(0xffffffffu, s,  o);
            sq += __shfl_xor_sync(0xffffffffu, sq, o);
        }
        float mu = s * (1.0f / D_MODEL);
        float var = sq * (1.0f / D_MODEL) - mu * mu;
        float rstd = rsqrtf(var + 1e-6f);
        #pragma unroll
        for (int i = 0; i < 8; ++i) {
            float4 gv = gr[lane + 32 * i];
            float4 bv = br[lane + 32 * i];
            float v0 = (v[i].x - mu) * rstd * gv.x + bv.x;
            float v1 = (v[i].y - mu) * rstd * gv.y + bv.y;
            float v2 = (v[i].z - mu) * rstd * gv.z + bv.z;
            float v3 = (v[i].w - mu) * rstd * gv.w + bv.w;
            uint2 o;
            o.x = pack2(v0, v1);
            o.y = pack2(v2, v3);
            orow[lane + 32 * i] = o;
        }
    }
}

// ---------------- LayerNorm: one WARP per row (for LN2) ----------------
__global__ void __launch_bounds__(256) ln_kernel(const float* __restrict__ x,
                                                 const float* __restrict__ g,
                                                 const float* __restrict__ b,
                                                 __half* __restrict__ out) {
    int warp = threadIdx.x >> 5, lane = threadIdx.x & 31;
    int row = blockIdx.x * 8 + warp;
    const float4* xr = (const float4*)(x + (size_t)row * D_MODEL);
    const float4* gr = (const float4*)g;
    const float4* br = (const float4*)b;
    uint2* orow = (uint2*)(out + (size_t)row * D_MODEL);

    float4 v[8];
    #pragma unroll
    for (int i = 0; i < 8; ++i) v[i] = xr[lane + 32 * i];

    float s = 0.f, sq = 0.f;
    #pragma unroll
    for (int i = 0; i < 8; ++i) {
        s  += v[i].x + v[i].y + v[i].z + v[i].w;
        sq += v[i].x*v[i].x + v[i].y*v[i].y + v[i].z*v[i].z + v[i].w*v[i].w;
    }
    #pragma unroll
    for (int o = 16; o > 0; o >>= 1) {
        s  += __shfl_xor_sync(0xffffffffu, s,  o);
        sq += __shfl_xor_sync(0xffffffffu, sq, o);
    }
    float mu = s * (1.0f / D_MODEL);
    float var = sq * (1.0f / D_MODEL) - mu * mu;
    float rstd = rsqrtf(var + 1e-6f);

    #pragma unroll
    for (int i = 0; i < 8; ++i) {
        float4 gv = gr[lane + 32 * i];
        float4 bv = br[lane + 32 * i];
        float v0 = (v[i].x - mu) * rstd * gv.x + bv.x;
        float v1 = (v[i].y - mu) * rstd * gv.y + bv.y;
        float v2 = (v[i].z - mu) * rstd * gv.z + bv.z;
        float v3 = (v[i].w - mu) * rstd * gv.w + bv.w;
        uint2 o;
        o.x = pack2(v0, v1);
        o.y = pack2(v2, v3);
        orow[lane + 32 * i] = o;
    }
}

// ---------------- FP16 GEMM: 256x128 CTA tile, 512 threads, 5 stages -------
// (R13-proven plateau configuration — frozen)
#define BM2 256
#define BN 128
#define BKH 32
#define PITCHB 80
#define STAGES 5
#define A_SZ (BM2 * PITCHB)                // 20480
#define STAGE_BYTES (A_SZ + BN * PITCHB)   // 30720

template<int EPI, int OUTHALF, int QSCALE>
__global__ void __launch_bounds__(512, 1) gemm_h(const __half* __restrict__ A,
                                                 const __half* __restrict__ Bw,
                                                 const float* __restrict__ bias,
                                                 const float* __restrict__ res,
                                                 void* __restrict__ Cout,
                                                 int M, int N, int K) {
    extern __shared__ char smraw[];
    uint32_t su = (uint32_t)__cvta_generic_to_shared(smraw);

    int tid = threadIdx.x;
    int m0 = blockIdx.y * BM2;
    int n0 = blockIdx.x * BN;
    int warp = tid >> 5, lane = tid & 31;
    int wm = (warp & 3) * 64;
    int wn = (warp >> 2) * 32;
    int r4 = lane >> 2, cc = lane & 3;

    float acc[4][4][4];
    #pragma unroll
    for (int i = 0; i < 4; ++i)
        #pragma unroll
        for (int j = 0; j < 4; ++j)
            #pragma unroll
            for (int k = 0; k < 4; ++k) acc[i][j][k] = 0.f;

    int arow = tid >> 1, apr = tid & 1;
    const __half* Ap = A + (size_t)(m0 + arow) * K + apr * 16;
    uint32_t dA = (uint32_t)(arow * PITCHB + apr * 32);
    int brow = tid >> 2, bch = tid & 3;
    const __half* Bp = Bw + (size_t)(n0 + brow) * K + bch * 8;
    uint32_t dB = (uint32_t)(A_SZ + brow * PITCHB + bch * 16);

    uint32_t aAddr = su + (uint32_t)((wm + (lane & 15)) * PITCHB + (lane >> 4) * 16);
    uint32_t bAddr = su + A_SZ +
        (uint32_t)((wn + (lane & 7) + ((lane >> 4) << 3)) * PITCHB +
                   ((lane >> 3) & 1) * 16);

    int ntiles = K / BKH;

    #pragma unroll
    for (int s = 0; s < STAGES - 1; ++s) {
        uint32_t sb = su + s * STAGE_BYTES;
        cp16(sb + dA, Ap + s * BKH);
        cp16(sb + dA + 16, Ap + s * BKH + 8);
        cp16(sb + dB, Bp + s * BKH);
        cp_commit();
    }

    int stq = 0;
    for (int t = 0; t < ntiles; ++t) {
        cp_wait3();
        __syncthreads();

        int tp = t + STAGES - 1;
        if (tp < ntiles) {
            int sp = stq + STAGES - 1;
            if (sp >= STAGES) sp -= STAGES;
            uint32_t sb = su + sp * STAGE_BYTES;
            cp16(sb + dA, Ap + tp * BKH);
            cp16(sb + dA + 16, Ap + tp * BKH + 8);
            cp16(sb + dB, Bp + tp * BKH);
        }
        cp_commit();

        uint32_t stg = stq * STAGE_BYTES;
        if (++stq == STAGES) stq = 0;
        #pragma unroll
        for (int ks = 0; ks < 2; ++ks) {
            uint32_t kof = stg + ks * 32;
            uint32_t af[4][4], bf[4][2];
            #pragma unroll
            for (int mt = 0; mt < 4; ++mt)
                ldsm4(af[mt][0], af[mt][1], af[mt][2], af[mt][3],
                      aAddr + kof + mt * (16 * PITCHB));
            ldsm4(bf[0][0], bf[0][1], bf[1][0], bf[1][1], bAddr + kof);
            ldsm4(bf[2][0], bf[2][1], bf[3][0], bf[3][1],
                  bAddr + kof + 16 * PITCHB);
            #pragma unroll
            for (int mt = 0; mt < 4; ++mt)
                #pragma unroll
                for (int nt = 0; nt < 4; ++nt)
                    mma_f16(acc[mt][nt], af[mt][0], af[mt][1], af[mt][2], af[mt][3],
                            bf[nt][0], bf[nt][1]);
        }
    }

    #pragma unroll
    for (int mt = 0; mt < 4; ++mt) {
        int row0 = m0 + wm + mt * 16 + r4;
        #pragma unroll
        for (int nt = 0; nt < 4; ++nt) {
            int col = n0 + wn + nt * 8 + cc * 2;
            float b0v = bias[col], b1v = bias[col + 1];
            float v0 = acc[mt][nt][0] + b0v;
            float v1 = acc[mt][nt][1] + b1v;
            float v2 = acc[mt][nt][2] + b0v;
            float v3 = acc[mt][nt][3] + b1v;
            if (EPI == 1) {
                v0 = gelu_exact(v0); v1 = gelu_exact(v1);
                v2 = gelu_exact(v2); v3 = gelu_exact(v3);
            }
            if (EPI == 2) {
                float2 r0 = *(const float2*)&res[(size_t)row0 * N + col];
                float2 r1 = *(const float2*)&res[(size_t)(row0 + 8) * N + col];
                v0 += r0.x; v1 += r0.y; v2 += r1.x; v3 += r1.y;
            }
            if (QSCALE) {
                if (col < 1024) {
                    v0 *= QSC; v1 *= QSC; v2 *= QSC; v3 *= QSC;
                }
            }
            if (OUTHALF) {
                __half* Ch = (__half*)Cout;
                *(uint32_t*)&Ch[(size_t)row0 * N + col]       = pack2(v0, v1);
                *(uint32_t*)&Ch[(size_t)(row0 + 8) * N + col] = pack2(v2, v3);
            } else {
                float* Cf = (float*)Cout;
                *(float2*)&Cf[(size_t)row0 * N + col]       = make_float2(v0, v1);
                *(float2*)&Cf[(size_t)(row0 + 8) * N + col] = make_float2(v2, v3);
            }
        }
    }
}

// ---------------- FP16 flash attention (R12-proven, frozen) ------
#define HP 72
#define Q_BYTES  (128 * HP * 2)
#define KV_STB   (64 * HP * 2)
#define KO_BYTES Q_BYTES
#define VO_BYTES (Q_BYTES + 2 * KV_STB)
#define ATTN_SMEM (Q_BYTES + 4 * KV_STB)

__global__ void __launch_bounds__(256) attn_h(const __half* __restrict__ qkv,
                                              __half* __restrict__ ctx) {
    extern __shared__ char asm_raw[];
    uint32_t base = (uint32_t)__cvta_generic_to_shared(asm_raw);

    int t = threadIdx.x;
    int warp = t >> 5, lane = t & 31;
    int r4 = lane >> 2, cc = lane & 3;
    int b = blockIdx.z, h = blockIdx.y;
    int s0 = blockIdx.x * 128;
    int wq = warp * 16;

    const __half* qbase = qkv + (size_t)(b * 1024 + s0) * 3072 + h * HEAD_D;
    const __half* kbase = qkv + (size_t)b * 1024 * 3072 + 1024 + h * HEAD_D;
    const __half* vbase = qkv + (size_t)b * 1024 * 3072 + 2048 + h * HEAD_D;

    #pragma unroll
    for (int p = 0; p < 4; ++p) {
        int j = t + 256 * p;
        int row = j >> 3, ch = j & 7;
        cp16(base + row * 144 + ch * 16, qbase + (size_t)row * 3072 + ch * 8);
    }
    #pragma unroll
    for (int p = 0; p < 2; ++p) {
        int j = t + 256 * p;
        int row = j >> 3, ch = j & 7;
        cp16(base + KO_BYTES + row * 144 + ch * 16,
             kbase + (size_t)row * 3072 + ch * 8);
        cp16(base + VO_BYTES + row * 144 + ch * 16,
             vbase + (size_t)row * 3072 + ch * 8);
    }
    cp_commit();

    uint32_t aQ = base + (uint32_t)((wq + (lane & 15)) * 144 + (lane >> 4) * 16);
    uint32_t bKoff = (uint32_t)(((lane & 7) + ((lane >> 4) << 3)) * 144 +
                                ((lane >> 3) & 1) * 16);
    int tsel = lane >> 3, tr = lane & 7;
    uint32_t bVoff = (uint32_t)(((tsel & 1) * 8 + tr) * 144 + (tsel >> 1) * 16);

    uint32_t qf[4][4];
    float mr_lo = -1e30f, mr_hi = -1e30f, l_lo = 0.f, l_hi = 0.f;
    float oacc[8][4];
    #pragma unroll
    for (int i = 0; i < 8; ++i)
        #pragma unroll
        for (int j = 0; j < 4; ++j) oacc[i][j] = 0.f;

    for (int it = 0; it < 16; ++it) {
        cp_wait0();
        __syncthreads();

        if (it + 1 < 16) {
            uint32_t st = ((it + 1) & 1) * KV_STB;
            const __half* kp = kbase + (size_t)(it + 1) * 64 * 3072;
            const __half* vp = vbase + (size_t)(it + 1) * 64 * 3072;
            #pragma unroll
            for (int p = 0; p < 2; ++p) {
                int j = t + 256 * p;
                int row = j >> 3, ch = j & 7;
                cp16(base + KO_BYTES + st + row * 144 + ch * 16,
                     kp + (size_t)row * 3072 + ch * 8);
                cp16(base + VO_BYTES + st + row * 144 + ch * 16,
                     vp + (size_t)row * 3072 + ch * 8);
            }
            cp_commit();
        }

        if (it == 0) {
            #pragma unroll
            for (int ks = 0; ks < 4; ++ks)
                ldsm4(qf[ks][0], qf[ks][1], qf[ks][2], qf[ks][3], aQ + ks * 32);
        }

        uint32_t stg = (it & 1) * KV_STB;
        uint32_t bK = base + KO_BYTES + stg + bKoff;
        uint32_t bV = base + VO_BYTES + stg + bVoff;

        float sacc[8][4];
        #pragma unroll
        for (int i = 0; i < 8; ++i)
            #pragma unroll
            for (int j = 0; j < 4; ++j) sacc[i][j] = 0.f;

        #pragma unroll
        for (int ks = 0; ks < 4; ++ks) {
            uint32_t bf[8][2];
            #pragma unroll
            for (int nb = 0; nb < 4; ++nb)
                ldsm4(bf[2*nb][0], bf[2*nb][1], bf[2*nb+1][0], bf[2*nb+1][1],
                      bK + nb * (16 * 144) + ks * 32);
            #pragma unroll
            for (int nt = 0; nt < 8; ++nt)
                mma_f16(sacc[nt], qf[ks][0], qf[ks][1], qf[ks][2], qf[ks][3],
                        bf[nt][0], bf[nt][1]);
        }

        float mlo = -1e30f, mhi = -1e30f;
        #pragma unroll
        for (int nt = 0; nt < 8; ++nt) {
            mlo = fmaxf(mlo, fmaxf(sacc[nt][0], sacc[nt][1]));
            mhi = fmaxf(mhi, fmaxf(sacc[nt][2], sacc[nt][3]));
        }
        mlo = fmaxf(mlo, __shfl_xor_sync(0xffffffffu, mlo, 1));
        mlo = fmaxf(mlo, __shfl_xor_sync(0xffffffffu, mlo, 2));
        mhi = fmaxf(mhi, __shfl_xor_sync(0xffffffffu, mhi, 1));
        mhi = fmaxf(mhi, __shfl_xor_sync(0xffffffffu, mhi, 2));
        float mn_lo = fmaxf(mr_lo, mlo), mn_hi = fmaxf(mr_hi, mhi);
        float al_lo = ex2(mr_lo - mn_lo), al_hi = ex2(mr_hi - mn_hi);

        float ps_lo = 0.f, ps_hi = 0.f;
        #pragma unroll
        for (int nt = 0; nt < 8; ++nt) {
            sacc[nt][0] = ex2(sacc[nt][0] - mn_lo);
            sacc[nt][1] = ex2(sacc[nt][1] - mn_lo);
            sacc[nt][2] = ex2(sacc[nt][2] - mn_hi);
            sacc[nt][3] = ex2(sacc[nt][3] - mn_hi);
            ps_lo += sacc[nt][0] + sacc[nt][1];
            ps_hi += sacc[nt][2] + sacc[nt][3];
        }
        ps_lo += __shfl_xor_sync(0xffffffffu, ps_lo, 1);
        ps_lo += __shfl_xor_sync(0xffffffffu, ps_lo, 2);
        ps_hi += __shfl_xor_sync(0xffffffffu, ps_hi, 1);
        ps_hi += __shfl_xor_sync(0xffffffffu, ps_hi, 2);
        l_lo = l_lo * al_lo + ps_lo;
        l_hi = l_hi * al_hi + ps_hi;
        mr_lo = mn_lo; mr_hi = mn_hi;
        #pragma unroll
        for (int nt = 0; nt < 8; ++nt) {
            oacc[nt][0] *= al_lo; oacc[nt][1] *= al_lo;
            oacc[nt][2] *= al_hi; oacc[nt][3] *= al_hi;
        }

        #pragma unroll
        for (int kk = 0; kk < 4; ++kk) {
            uint32_t a0 = pack2(sacc[2*kk][0],   sacc[2*kk][1]);
            uint32_t a1 = pack2(sacc[2*kk][2],   sacc[2*kk][3]);
            uint32_t a2 = pack2(sacc[2*kk+1][0], sacc[2*kk+1][1]);
            uint32_t a3 = pack2(sacc[2*kk+1][2], sacc[2*kk+1][3]);
            uint32_t vf[8][2];
            #pragma unroll
            for (int db = 0; db < 4; ++db)
                ldsm4t(vf[2*db][0], vf[2*db][1], vf[2*db+1][0], vf[2*db+1][1],
                       bV + kk * (16 * 144) + db * 32);
            #pragma unroll
            for (int nt = 0; nt < 8; ++nt)
                mma_f16(oacc[nt], a0, a1, a2, a3, vf[nt][0], vf[nt][1]);
        }
    }

    float il_lo = 1.f / l_lo, il_hi = 1.f / l_hi;
    int row_lo = b * 1024 + s0 + wq + r4;
    #pragma unroll
    for (int nt = 0; nt < 8; ++nt) {
        int col = h * HEAD_D + nt * 8 + cc * 2;
        *(uint32_t*)&ctx[(size_t)row_lo * D_MODEL + col] =
            pack2(oacc[nt][0] * il_lo, oacc[nt][1] * il_lo);
        *(uint32_t*)&ctx[(size_t)(row_lo + 8) * D_MODEL + col] =
            pack2(oacc[nt][2] * il_hi, oacc[nt][3] * il_hi);
    }
}

// ---------------- launch ----------------
extern "C" void kernel_launch(void* const* d_in, const int* in_sizes, int n_in,
                              void* d_out, int out_size) {
    const float* x      = (const float*)d_in[0];
    const float* qkv_w  = (const float*)d_in[1];
    const float* qkv_b  = (const float*)d_in[2];
    const float* proj_w = (const float*)d_in[3];
    const float* proj_b = (const float*)d_in[4];
    const float* fc1_w  = (const float*)d_in[5];
    const float* fc1_b  = (const float*)d_in[6];
    const float* fc2_w  = (const float*)d_in[7];
    const float* fc2_b  = (const float*)d_in[8];
    const float* ln1_g  = (const float*)d_in[9];
    const float* ln1_b  = (const float*)d_in[10];
    const float* ln2_g  = (const float*)d_in[11];
    const float* ln2_b  = (const float*)d_in[12];
    float* out = (float*)d_out;

    __half *h, *qkv, *ctx, *ff, *wq, *wp, *w1, *w2;
    float *x2;
    cudaGetSymbolAddress((void**)&h,   g_h);
    cudaGetSymbolAddress((void**)&qkv, g_qkv);
    cudaGetSymbolAddress((void**)&ctx, g_ctx);
    cudaGetSymbolAddress((void**)&x2,  g_x2);
    cudaGetSymbolAddress((void**)&ff,  g_ff);
    cudaGetSymbolAddress((void**)&wq,  g_wq);
    cudaGetSymbolAddress((void**)&wp,  g_wp);
    cudaGetSymbolAddress((void**)&w1,  g_w1);
    cudaGetSymbolAddress((void**)&w2,  g_w2);

    int gemm_smem = STAGES * STAGE_BYTES;   // 153600
    cudaFuncSetAttribute(gemm_h<0,1,1>, cudaFuncAttributeMaxDynamicSharedMemorySize, gemm_smem);
    cudaFuncSetAttribute(gemm_h<2,0,0>, cudaFuncAttributeMaxDynamicSharedMemorySize, gemm_smem);
    cudaFuncSetAttribute(gemm_h<1,1,0>, cudaFuncAttributeMaxDynamicSharedMemorySize, gemm_smem);
    cudaFuncSetAttribute(attn_h, cudaFuncAttributeMaxDynamicSharedMemorySize, ATTN_SMEM);

    // fused: weight conversion + LN1 in one launch
    prep_kernel<<<CONV_BLOCKS + LN_BLOCKS, 256>>>(
        qkv_w, proj_w, fc1_w, fc2_w, wq, wp, w1, w2, x, ln1_g, ln1_b, h);

    gemm_h<0,1,1><<<dim3(3 * D_MODEL / BN, N_TOK / BM2), 512, gemm_smem>>>(
        h, wq, qkv_b, nullptr, qkv, N_TOK, 3 * D_MODEL, D_MODEL);
    attn_h<<<dim3(1024 / 128, N_HEAD, 8), 256, ATTN_SMEM>>>(qkv, ctx);
    gemm_h<2,0,0><<<dim3(D_MODEL / BN, N_TOK / BM2), 512, gemm_smem>>>(
        ctx, wp, proj_b, x, x2, N_TOK, D_MODEL, D_MODEL);
    ln_kernel<<<N_TOK / 8, 256>>>(x2, ln2_g, ln2_b, h);
    gemm_h<1,1,0><<<dim3(FF_DIM / BN, N_TOK / BM2), 512, gemm_smem>>>(
        h, w1, fc1_b, nullptr, ff, N_TOK, FF_DIM, D_MODEL);
    gemm_h<2,0,0><<<dim3(D_MODEL / BN, N_TOK / BM2), 512, gemm_smem>>>(
        ff, w2, fc2_b, x2, out, N_TOK, D_MODEL, FF_DIM);
}

// round 16
// speedup vs baseline: 1.2139x; 1.0069x over previous
#include <cuda_runtime.h>
#include <cuda_fp16.h>
#include <math.h>
#include <stdint.h>

#define D_MODEL 1024
#define N_TOK   8192
#define FF_DIM  4096
#define N_HEAD  16
#define HEAD_D  64

__device__ __half g_h  [N_TOK * D_MODEL];
__device__ __half g_qkv[N_TOK * 3 * D_MODEL];
__device__ __half g_ctx[N_TOK * D_MODEL];
__device__ float  g_x2 [N_TOK * D_MODEL];
__device__ __half g_ff [N_TOK * FF_DIM];
__device__ __half g_wq[3 * D_MODEL * D_MODEL];
__device__ __half g_wp[D_MODEL * D_MODEL];
__device__ __half g_w1[FF_DIM * D_MODEL];
__device__ __half g_w2[D_MODEL * FF_DIM];

// q pre-scale: 1/sqrt(64) * log2(e)
#define QSC 0.18033688011112042f

// ---------------- helpers ----------------
__device__ __forceinline__ float gelu_exact(float v) {
    return 0.5f * v * (1.0f + erff(v * 0.70710678118654752440f));
}
__device__ __forceinline__ float ex2(float x) {
    float r;
    asm("ex2.approx.ftz.f32 %0, %1;" : "=f"(r) : "f"(x));
    return r;
}
__device__ __forceinline__ void mma_f16(float d[4], uint32_t a0, uint32_t a1,
                                        uint32_t a2, uint32_t a3,
                                        uint32_t b0, uint32_t b1) {
    asm volatile(
        "mma.sync.aligned.m16n8k16.row.col.f32.f16.f16.f32 "
        "{%0,%1,%2,%3}, {%4,%5,%6,%7}, {%8,%9}, {%0,%1,%2,%3};\n"
        : "+f"(d[0]), "+f"(d[1]), "+f"(d[2]), "+f"(d[3])
        : "r"(a0), "r"(a1), "r"(a2), "r"(a3), "r"(b0), "r"(b1));
}
// f16-accumulator variant (D/C are 2 packed regs)
__device__ __forceinline__ void mma_h16(uint32_t& d0, uint32_t& d1,
                                        uint32_t a0, uint32_t a1,
                                        uint32_t a2, uint32_t a3,
                                        uint32_t b0, uint32_t b1) {
    asm volatile(
        "mma.sync.aligned.m16n8k16.row.col.f16.f16.f16.f16 "
        "{%0,%1}, {%2,%3,%4,%5}, {%6,%7}, {%0,%1};\n"
        : "+r"(d0), "+r"(d1)
        : "r"(a0), "r"(a1), "r"(a2), "r"(a3), "r"(b0), "r"(b1));
}
__device__ __forceinline__ void ldsm4(uint32_t& r0, uint32_t& r1, uint32_t& r2,
                                      uint32_t& r3, uint32_t addr) {
    asm volatile("ldmatrix.sync.aligned.m8n8.x4.shared.b16 {%0,%1,%2,%3}, [%4];"
                 : "=r"(r0), "=r"(r1), "=r"(r2), "=r"(r3) : "r"(addr));
}
__device__ __forceinline__ void ldsm4t(uint32_t& r0, uint32_t& r1, uint32_t& r2,
                                       uint32_t& r3, uint32_t addr) {
    asm volatile("ldmatrix.sync.aligned.m8n8.x4.trans.shared.b16 {%0,%1,%2,%3}, [%4];"
                 : "=r"(r0), "=r"(r1), "=r"(r2), "=r"(r3) : "r"(addr));
}
__device__ __forceinline__ void cp16(uint32_t smem, const void* g) {
    asm volatile("cp.async.cg.shared.global [%0], [%1], 16;" :: "r"(smem), "l"(g));
}
__device__ __forceinline__ void cp_commit() {
    asm volatile("cp.async.commit_group;");
}
__device__ __forceinline__ void cp_wait3() {
    asm volatile("cp.async.wait_group 3;");
}
__device__ __forceinline__ void cp_wait0() {
    asm volatile("cp.async.wait_group 0;");
}
__device__ __forceinline__ uint32_t pack2(float a, float b) {
    __half2 h = __floats2half2_rn(a, b);
    return *(uint32_t*)&h;
}
__device__ __forceinline__ float2 unpack2(uint32_t u) {
    return __half22float2(*(__half2*)&u);
}

// ---------------- fused prep: weight convert (MLP=4) + LN1 ----------------
#define WQ_Q 786432
#define WP_Q 262144
#define W1_Q 1048576
#define W2_Q 1048576
#define TOT_Q (WQ_Q + WP_Q + W1_Q + W2_Q)   // 3145728
#define CONV_BLOCKS (TOT_Q / 1024)           // 3072 (4 quads per thread)
#define LN_BLOCKS   (N_TOK / 8)              // 1024

__global__ void __launch_bounds__(256) prep_kernel(
        const float* __restrict__ qw, const float* __restrict__ pw,
        const float* __restrict__ w1, const float* __restrict__ w2,
        __half* __restrict__ oq, __half* __restrict__ op,
        __half* __restrict__ o1, __half* __restrict__ o2,
        const float* __restrict__ x, const float* __restrict__ lg,
        const float* __restrict__ lb, __half* __restrict__ hout) {
    if (blockIdx.x < CONV_BLOCKS) {
        int ibase = blockIdx.x * 1024 + threadIdx.x;
        #pragma unroll
        for (int k = 0; k < 4; ++k) {
            int i = ibase + 256 * k;
            const float* src; __half* dst; int off;
            if (i < WQ_Q) { src = qw; dst = oq; off = i; }
            else if (i < WQ_Q + WP_Q) { src = pw; dst = op; off = i - WQ_Q; }
            else if (i < WQ_Q + WP_Q + W1_Q) { src = w1; dst = o1; off = i - WQ_Q - WP_Q; }
            else { src = w2; dst = o2; off = i - WQ_Q - WP_Q - W1_Q; }
            float4 v = ((const float4*)src)[off];
            uint2 o;
            o.x = pack2(v.x, v.y);
            o.y = pack2(v.z, v.w);
            ((uint2*)dst)[off] = o;
        }
    } else {
        int warp = threadIdx.x >> 5, lane = threadIdx.x & 31;
        int row = (blockIdx.x - CONV_BLOCKS) * 8 + warp;
        const float4* xr = (const float4*)(x + (size_t)row * D_MODEL);
        const float4* gr = (const float4*)lg;
        const float4* br = (const float4*)lb;
        uint2* orow = (uint2*)(hout + (size_t)row * D_MODEL);

        float4 v[8];
        #pragma unroll
        for (int i = 0; i < 8; ++i) v[i] = xr[lane + 32 * i];
        float s = 0.f, sq = 0.f;
        #pragma unroll
        for (int i = 0; i < 8; ++i) {
            s  += v[i].x + v[i].y + v[i].z + v[i].w;
            sq += v[i].x*v[i].x + v[i].y*v[i].y + v[i].z*v[i].z + v[i].w*v[i].w;
        }
        #pragma unroll
        for (int o = 16; o > 0; o >>= 1) {
            s  += __shfl_xor_sync(0xffffffffu, s,  o);
            sq += __shfl_xor_sync(0xffffffffu, sq, o);
        }
        float mu = s * (1.0f / D_MODEL);
        float var = sq * (1.0f / D_MODEL) - mu * mu;
        float rstd = rsqrtf(var + 1e-6f);
        #pragma unroll
        for (int i = 0; i < 8; ++i) {
            float4 gv = gr[lane + 32 * i];
            float4 bv = br[lane + 32 * i];
            float v0 = (v[i].x - mu) * rstd * gv.x + bv.x;
            float v1 = (v[i].y - mu) * rstd * gv.y + bv.y;
            float v2 = (v[i].z - mu) * rstd * gv.z + bv.z;
            float v3 = (v[i].w - mu) * rstd * gv.w + bv.w;
            uint2 o;
            o.x = pack2(v0, v1);
            o.y = pack2(v2, v3);
            orow[lane + 32 * i] = o;
        }
    }
}

// ---------------- LayerNorm: one WARP per row (LN2) ----------------
__global__ void __launch_bounds__(256) ln_kernel(const float* __restrict__ x,
                                                 const float* __restrict__ g,
                                                 const float* __restrict__ b,
                                                 __half* __restrict__ out) {
    int warp = threadIdx.x >> 5, lane = threadIdx.x & 31;
    int row = blockIdx.x * 8 + warp;
    const float4* xr = (const float4*)(x + (size_t)row * D_MODEL);
    const float4* gr = (const float4*)g;
    const float4* br = (const float4*)b;
    uint2* orow = (uint2*)(out + (size_t)row * D_MODEL);

    float4 v[8];
    #pragma unroll
    for (int i = 0; i < 8; ++i) v[i] = xr[lane + 32 * i];

    float s = 0.f, sq = 0.f;
    #pragma unroll
    for (int i = 0; i < 8; ++i) {
        s  += v[i].x + v[i].y + v[i].z + v[i].w;
        sq += v[i].x*v[i].x + v[i].y*v[i].y + v[i].z*v[i].z + v[i].w*v[i].w;
    }
    #pragma unroll
    for (int o = 16; o > 0; o >>= 1) {
        s  += __shfl_xor_sync(0xffffffffu, s,  o);
        sq += __shfl_xor_sync(0xffffffffu, sq, o);
    }
    float mu = s * (1.0f / D_MODEL);
    float var = sq * (1.0f / D_MODEL) - mu * mu;
    float rstd = rsqrtf(var + 1e-6f);

    #pragma unroll
    for (int i = 0; i < 8; ++i) {
        float4 gv = gr[lane + 32 * i];
        float4 bv = br[lane + 32 * i];
        float v0 = (v[i].x - mu) * rstd * gv.x + bv.x;
        float v1 = (v[i].y - mu) * rstd * gv.y + bv.y;
        float v2 = (v[i].z - mu) * rstd * gv.z + bv.z;
        float v3 = (v[i].w - mu) * rstd * gv.w + bv.w;
        uint2 o;
        o.x = pack2(v0, v1);
        o.y = pack2(v2, v3);
        orow[lane + 32 * i] = o;
    }
}

// ---------------- FP16 GEMM (R13-proven plateau config, frozen) -------
#define BM2 256
#define BN 128
#define BKH 32
#define PITCHB 80
#define STAGES 5
#define A_SZ (BM2 * PITCHB)                // 20480
#define STAGE_BYTES (A_SZ + BN * PITCHB)   // 30720

template<int EPI, int OUTHALF, int QSCALE>
__global__ void __launch_bounds__(512, 1) gemm_h(const __half* __restrict__ A,
                                                 const __half* __restrict__ Bw,
                                                 const float* __restrict__ bias,
                                                 const float* __restrict__ res,
                                                 void* __restrict__ Cout,
                                                 int M, int N, int K) {
    extern __shared__ char smraw[];
    uint32_t su = (uint32_t)__cvta_generic_to_shared(smraw);

    int tid = threadIdx.x;
    int m0 = blockIdx.y * BM2;
    int n0 = blockIdx.x * BN;
    int warp = tid >> 5, lane = tid & 31;
    int wm = (warp & 3) * 64;
    int wn = (warp >> 2) * 32;
    int r4 = lane >> 2, cc = lane & 3;

    float acc[4][4][4];
    #pragma unroll
    for (int i = 0; i < 4; ++i)
        #pragma unroll
        for (int j = 0; j < 4; ++j)
            #pragma unroll
            for (int k = 0; k < 4; ++k) acc[i][j][k] = 0.f;

    int arow = tid >> 1, apr = tid & 1;
    const __half* Ap = A + (size_t)(m0 + arow) * K + apr * 16;
    uint32_t dA = (uint32_t)(arow * PITCHB + apr * 32);
    int brow = tid >> 2, bch = tid & 3;
    const __half* Bp = Bw + (size_t)(n0 + brow) * K + bch * 8;
    uint32_t dB = (uint32_t)(A_SZ + brow * PITCHB + bch * 16);

    uint32_t aAddr = su + (uint32_t)((wm + (lane & 15)) * PITCHB + (lane >> 4) * 16);
    uint32_t bAddr = su + A_SZ +
        (uint32_t)((wn + (lane & 7) + ((lane >> 4) << 3)) * PITCHB +
                   ((lane >> 3) & 1) * 16);

    int ntiles = K / BKH;

    #pragma unroll
    for (int s = 0; s < STAGES - 1; ++s) {
        uint32_t sb = su + s * STAGE_BYTES;
        cp16(sb + dA, Ap + s * BKH);
        cp16(sb + dA + 16, Ap + s * BKH + 8);
        cp16(sb + dB, Bp + s * BKH);
        cp_commit();
    }

    int stq = 0;
    for (int t = 0; t < ntiles; ++t) {
        cp_wait3();
        __syncthreads();

        int tp = t + STAGES - 1;
        if (tp < ntiles) {
            int sp = stq + STAGES - 1;
            if (sp >= STAGES) sp -= STAGES;
            uint32_t sb = su + sp * STAGE_BYTES;
            cp16(sb + dA, Ap + tp * BKH);
            cp16(sb + dA + 16, Ap + tp * BKH + 8);
            cp16(sb + dB, Bp + tp * BKH);
        }
        cp_commit();

        uint32_t stg = stq * STAGE_BYTES;
        if (++stq == STAGES) stq = 0;
        #pragma unroll
        for (int ks = 0; ks < 2; ++ks) {
            uint32_t kof = stg + ks * 32;
            uint32_t af[4][4], bf[4][2];
            #pragma unroll
            for (int mt = 0; mt < 4; ++mt)
                ldsm4(af[mt][0], af[mt][1], af[mt][2], af[mt][3],
                      aAddr + kof + mt * (16 * PITCHB));
            ldsm4(bf[0][0], bf[0][1], bf[1][0], bf[1][1], bAddr + kof);
            ldsm4(bf[2][0], bf[2][1], bf[3][0], bf[3][1],
                  bAddr + kof + 16 * PITCHB);
            #pragma unroll
            for (int mt = 0; mt < 4; ++mt)
                #pragma unroll
                for (int nt = 0; nt < 4; ++nt)
                    mma_f16(acc[mt][nt], af[mt][0], af[mt][1], af[mt][2], af[mt][3],
                            bf[nt][0], bf[nt][1]);
        }
    }

    #pragma unroll
    for (int mt = 0; mt < 4; ++mt) {
        int row0 = m0 + wm + mt * 16 + r4;
        #pragma unroll
        for (int nt = 0; nt < 4; ++nt) {
            int col = n0 + wn + nt * 8 + cc * 2;
            float b0v = bias[col], b1v = bias[col + 1];
            float v0 = acc[mt][nt][0] + b0v;
            float v1 = acc[mt][nt][1] + b1v;
            float v2 = acc[mt][nt][2] + b0v;
            float v3 = acc[mt][nt][3] + b1v;
            if (EPI == 1) {
                v0 = gelu_exact(v0); v1 = gelu_exact(v1);
                v2 = gelu_exact(v2); v3 = gelu_exact(v3);
            }
            if (EPI == 2) {
                float2 r0 = *(const float2*)&res[(size_t)row0 * N + col];
                float2 r1 = *(const float2*)&res[(size_t)(row0 + 8) * N + col];
                v0 += r0.x; v1 += r0.y; v2 += r1.x; v3 += r1.y;
            }
            if (QSCALE) {
                if (col < 1024) {
                    v0 *= QSC; v1 *= QSC; v2 *= QSC; v3 *= QSC;
                }
            }
            if (OUTHALF) {
                __half* Ch = (__half*)Cout;
                *(uint32_t*)&Ch[(size_t)row0 * N + col]       = pack2(v0, v1);
                *(uint32_t*)&Ch[(size_t)(row0 + 8) * N + col] = pack2(v2, v3);
            } else {
                float* Cf = (float*)Cout;
                *(float2*)&Cf[(size_t)row0 * N + col]       = make_float2(v0, v1);
                *(float2*)&Cf[(size_t)(row0 + 8) * N + col] = make_float2(v2, v3);
            }
        }
    }
}

// ---------------- FP16 flash attention: f16-accumulator probe ------
#define HP 72
#define Q_BYTES  (128 * HP * 2)
#define KV_STB   (64 * HP * 2)
#define KO_BYTES Q_BYTES
#define VO_BYTES (Q_BYTES + 2 * KV_STB)
#define ATTN_SMEM (Q_BYTES + 4 * KV_STB)

__global__ void __launch_bounds__(256) attn_h(const __half* __restrict__ qkv,
                                              __half* __restrict__ ctx) {
    extern __shared__ char asm_raw[];
    uint32_t base = (uint32_t)__cvta_generic_to_shared(asm_raw);

    int t = threadIdx.x;
    int warp = t >> 5, lane = t & 31;
    int r4 = lane >> 2, cc = lane & 3;
    int b = blockIdx.z, h = blockIdx.y;
    int s0 = blockIdx.x * 128;
    int wq = warp * 16;

    const __half* qbase = qkv + (size_t)(b * 1024 + s0) * 3072 + h * HEAD_D;
    const __half* kbase = qkv + (size_t)b * 1024 * 3072 + 1024 + h * HEAD_D;
    const __half* vbase = qkv + (size_t)b * 1024 * 3072 + 2048 + h * HEAD_D;

    #pragma unroll
    for (int p = 0; p < 4; ++p) {
        int j = t + 256 * p;
        int row = j >> 3, ch = j & 7;
        cp16(base + row * 144 + ch * 16, qbase + (size_t)row * 3072 + ch * 8);
    }
    #pragma unroll
    for (int p = 0; p < 2; ++p) {
        int j = t + 256 * p;
        int row = j >> 3, ch = j & 7;
        cp16(base + KO_BYTES + row * 144 + ch * 16,
             kbase + (size_t)row * 3072 + ch * 8);
        cp16(base + VO_BYTES + row * 144 + ch * 16,
             vbase + (size_t)row * 3072 + ch * 8);
    }
    cp_commit();

    uint32_t aQ = base + (uint32_t)((wq + (lane & 15)) * 144 + (lane >> 4) * 16);
    uint32_t bKoff = (uint32_t)(((lane & 7) + ((lane >> 4) << 3)) * 144 +
                                ((lane >> 3) & 1) * 16);
    int tsel = lane >> 3, tr = lane & 7;
    uint32_t bVoff = (uint32_t)(((tsel & 1) * 8 + tr) * 144 + (tsel >> 1) * 16);

    uint32_t qf[4][4];
    float mr_lo = -1e30f, mr_hi = -1e30f, l_lo = 0.f, l_hi = 0.f;
    float oacc[8][4];
    #pragma unroll
    for (int i = 0; i < 8; ++i)
        #pragma unroll
        for (int j = 0; j < 4; ++j) oacc[i][j] = 0.f;

    for (int it = 0; it < 16; ++it) {
        cp_wait0();
        __syncthreads();

        if (it + 1 < 16) {
            uint32_t st = ((it + 1) & 1) * KV_STB;
            const __half* kp = kbase + (size_t)(it + 1) * 64 * 3072;
            const __half* vp = vbase + (size_t)(it + 1) * 64 * 3072;
            #pragma unroll
            for (int p = 0; p < 2; ++p) {
                int j = t + 256 * p;
                int row = j >> 3, ch = j & 7;
                cp16(base + KO_BYTES + st + row * 144 + ch * 16,
                     kp + (size_t)row * 3072 + ch * 8);
                cp16(base + VO_BYTES + st + row * 144 + ch * 16,
                     vp + (size_t)row * 3072 + ch * 8);
            }
            cp_commit();
        }

        if (it == 0) {
            #pragma unroll
            for (int ks = 0; ks < 4; ++ks)
                ldsm4(qf[ks][0], qf[ks][1], qf[ks][2], qf[ks][3], aQ + ks * 32);
        }

        uint32_t stg = (it & 1) * KV_STB;
        uint32_t bK = base + KO_BYTES + stg + bKoff;
        uint32_t bV = base + VO_BYTES + stg + bVoff;

        // ---- S = Q K^T with f16 accumulator (K=64, 4 mmas) ----
        uint32_t s16[8][2];
        #pragma unroll
        for (int i = 0; i < 8; ++i) { s16[i][0] = 0u; s16[i][1] = 0u; }

        #pragma unroll
        for (int ks = 0; ks < 4; ++ks) {
            uint32_t bf[8][2];
            #pragma unroll
            for (int nb = 0; nb < 4; ++nb)
                ldsm4(bf[2*nb][0], bf[2*nb][1], bf[2*nb+1][0], bf[2*nb+1][1],
                      bK + nb * (16 * 144) + ks * 32);
            #pragma unroll
            for (int nt = 0; nt < 8; ++nt)
                mma_h16(s16[nt][0], s16[nt][1],
                        qf[ks][0], qf[ks][1], qf[ks][2], qf[ks][3],
                        bf[nt][0], bf[nt][1]);
        }

        // unpack to fp32
        float sf[8][4];
        #pragma unroll
        for (int nt = 0; nt < 8; ++nt) {
            float2 lo = unpack2(s16[nt][0]);
            float2 hi = unpack2(s16[nt][1]);
            sf[nt][0] = lo.x; sf[nt][1] = lo.y;
            sf[nt][2] = hi.x; sf[nt][3] = hi.y;
        }

        // ---- online softmax (base 2) ----
        float mlo = -1e30f, mhi = -1e30f;
        #pragma unroll
        for (int nt = 0; nt < 8; ++nt) {
            mlo = fmaxf(mlo, fmaxf(sf[nt][0], sf[nt][1]));
            mhi = fmaxf(mhi, fmaxf(sf[nt][2], sf[nt][3]));
        }
        mlo = fmaxf(mlo, __shfl_xor_sync(0xffffffffu, mlo, 1));
        mlo = fmaxf(mlo, __shfl_xor_sync(0xffffffffu, mlo, 2));
        mhi = fmaxf(mhi, __shfl_xor_sync(0xffffffffu, mhi, 1));
        mhi = fmaxf(mhi, __shfl_xor_sync(0xffffffffu, mhi, 2));
        float mn_lo = fmaxf(mr_lo, mlo), mn_hi = fmaxf(mr_hi, mhi);
        float al_lo = ex2(mr_lo - mn_lo), al_hi = ex2(mr_hi - mn_hi);

        float ps_lo = 0.f, ps_hi = 0.f;
        #pragma unroll
        for (int nt = 0; nt < 8; ++nt) {
            sf[nt][0] = ex2(sf[nt][0] - mn_lo);
            sf[nt][1] = ex2(sf[nt][1] - mn_lo);
            sf[nt][2] = ex2(sf[nt][2] - mn_hi);
            sf[nt][3] = ex2(sf[nt][3] - mn_hi);
            ps_lo += sf[nt][0] + sf[nt][1];
            ps_hi += sf[nt][2] + sf[nt][3];
        }
        ps_lo += __shfl_xor_sync(0xffffffffu, ps_lo, 1);
        ps_lo += __shfl_xor_sync(0xffffffffu, ps_lo, 2);
        ps_hi += __shfl_xor_sync(0xffffffffu, ps_hi, 1);
        ps_hi += __shfl_xor_sync(0xffffffffu, ps_hi, 2);
        l_lo = l_lo * al_lo + ps_lo;
        l_hi = l_hi * al_hi + ps_hi;
        mr_lo = mn_lo; mr_hi = mn_hi;

        // ---- O: pv16 = P V (f16 acc, fresh per tile), then fp32 flush ----
        uint32_t pv16[8][2];
        #pragma unroll
        for (int i = 0; i < 8; ++i) { pv16[i][0] = 0u; pv16[i][1] = 0u; }

        #pragma unroll
        for (int kk = 0; kk < 4; ++kk) {
            uint32_t a0 = pack2(sf[2*kk][0],   sf[2*kk][1]);
            uint32_t a1 = pack2(sf[2*kk][2],   sf[2*kk][3]);
            uint32_t a2 = pack2(sf[2*kk+1][0], sf[2*kk+1][1]);
            uint32_t a3 = pack2(sf[2*kk+1][2], sf[2*kk+1][3]);
            uint32_t vf[8][2];
            #pragma unroll
            for (int db = 0; db < 4; ++db)
                ldsm4t(vf[2*db][0], vf[2*db][1], vf[2*db+1][0], vf[2*db+1][1],
                       bV + kk * (16 * 144) + db * 32);
            #pragma unroll
            for (int nt = 0; nt < 8; ++nt)
                mma_h16(pv16[nt][0], pv16[nt][1], a0, a1, a2, a3,
                        vf[nt][0], vf[nt][1]);
        }

        #pragma unroll
        for (int nt = 0; nt < 8; ++nt) {
            float2 lo = unpack2(pv16[nt][0]);
            float2 hi = unpack2(pv16[nt][1]);
            oacc[nt][0] = fmaf(oacc[nt][0], al_lo, lo.x);
            oacc[nt][1] = fmaf(oacc[nt][1], al_lo, lo.y);
            oacc[nt][2] = fmaf(oacc[nt][2], al_hi, hi.x);
            oacc[nt][3] = fmaf(oacc[nt][3], al_hi, hi.y);
        }
    }

    float il_lo = 1.f / l_lo, il_hi = 1.f / l_hi;
    int row_lo = b * 1024 + s0 + wq + r4;
    #pragma unroll
    for (int nt = 0; nt < 8; ++nt) {
        int col = h * HEAD_D + nt * 8 + cc * 2;
        *(uint32_t*)&ctx[(size_t)row_lo * D_MODEL + col] =
            pack2(oacc[nt][0] * il_lo, oacc[nt][1] * il_lo);
        *(uint32_t*)&ctx[(size_t)(row_lo + 8) * D_MODEL + col] =
            pack2(oacc[nt][2] * il_hi, oacc[nt][3] * il_hi);
    }
}

// ---------------- launch ----------------
extern "C" void kernel_launch(void* const* d_in, const int* in_sizes, int n_in,
                              void* d_out, int out_size) {
    const float* x      = (const float*)d_in[0];
    const float* qkv_w  = (const float*)d_in[1];
    const float* qkv_b  = (const float*)d_in[2];
    const float* proj_w = (const float*)d_in[3];
    const float* proj_b = (const float*)d_in[4];
    const float* fc1_w  = (const float*)d_in[5];
    const float* fc1_b  = (const float*)d_in[6];
    const float* fc2_w  = (const float*)d_in[7];
    const float* fc2_b  = (const float*)d_in[8];
    const float* ln1_g  = (const float*)d_in[9];
    const float* ln1_b  = (const float*)d_in[10];
    const float* ln2_g  = (const float*)d_in[11];
    const float* ln2_b  = (const float*)d_in[12];
    float* out = (float*)d_out;

    __half *h, *qkv, *ctx, *ff, *wq, *wp, *w1, *w2;
    float *x2;
    cudaGetSymbolAddress((void**)&h,   g_h);
    cudaGetSymbolAddress((void**)&qkv, g_qkv);
    cudaGetSymbolAddress((void**)&ctx, g_ctx);
    cudaGetSymbolAddress((void**)&x2,  g_x2);
    cudaGetSymbolAddress((void**)&ff,  g_ff);
    cudaGetSymbolAddress((void**)&wq,  g_wq);
    cudaGetSymbolAddress((void**)&wp,  g_wp);
    cudaGetSymbolAddress((void**)&w1,  g_w1);
    cudaGetSymbolAddress((void**)&w2,  g_w2);

    int gemm_smem = STAGES * STAGE_BYTES;   // 153600
    cudaFuncSetAttribute(gemm_h<0,1,1>, cudaFuncAttributeMaxDynamicSharedMemorySize, gemm_smem);
    cudaFuncSetAttribute(gemm_h<2,0,0>, cudaFuncAttributeMaxDynamicSharedMemorySize, gemm_smem);
    cudaFuncSetAttribute(gemm_h<1,1,0>, cudaFuncAttributeMaxDynamicSharedMemorySize, gemm_smem);
    cudaFuncSetAttribute(attn_h, cudaFuncAttributeMaxDynamicSharedMemorySize, ATTN_SMEM);

    prep_kernel<<<CONV_BLOCKS + LN_BLOCKS, 256>>>(
        qkv_w, proj_w, fc1_w, fc2_w, wq, wp, w1, w2, x, ln1_g, ln1_b, h);

    gemm_h<0,1,1><<<dim3(3 * D_MODEL / BN, N_TOK / BM2), 512, gemm_smem>>>(
        h, wq, qkv_b, nullptr, qkv, N_TOK, 3 * D_MODEL, D_MODEL);
    attn_h<<<dim3(1024 / 128, N_HEAD, 8), 256, ATTN_SMEM>>>(qkv, ctx);
    gemm_h<2,0,0><<<dim3(D_MODEL / BN, N_TOK / BM2), 512, gemm_smem>>>(
        ctx, wp, proj_b, x, x2, N_TOK, D_MODEL, D_MODEL);
    ln_kernel<<<N_TOK / 8, 256>>>(x2, ln2_g, ln2_b, h);
    gemm_h<1,1,0><<<dim3(FF_DIM / BN, N_TOK / BM2), 512, gemm_smem>>>(
        h, w1, fc1_b, nullptr, ff, N_TOK, FF_DIM, D_MODEL);
    gemm_h<2,0,0><<<dim3(D_MODEL / BN, N_TOK / BM2), 512, gemm_smem>>>(
        ff, w2, fc2_b, x2, out, N_TOK, D_MODEL, FF_DIM);
}